// round 8
// baseline (speedup 1.0000x reference)
#include <cuda_runtime.h>
#include <cuda_fp16.h>
#include <cstdint>

#define B_    2
#define S_    2048
#define H_    2048
#define NH    16
#define HD    128
#define MTOT  (B_ * S_)           // 4096
#define SCALE 11.313708498984761f // sqrt(128)
#define HH    ((size_t)H_ * H_)
#define LOSCL 2048.0f
#define INVLO 4.8828125e-4f       // 1/2048

// GEMM tiling
#define BK      32
#define NCH     (H_ / BK)
#define TSTRIDE 40
#define TILE_B  (128 * TSTRIDE * 2)   // 10240 B
#define BUF_B   (4 * TILE_B)          // 3-term: Ah,Al,Wh,Wl
#define BUF1_B  (2 * TILE_B)          // 1-term: A,W
#define GEMM_SMEM (2 * BUF_B)         // 81920 B
#define OUT_SMEM  (2 * BUF1_B)        // 40960 B

// Attention smem: 5 half tiles [128][136] (Qh,Ql,Kh,Kl,Vh)
#define AST 136
#define ATILE (128 * AST)
#define ATTN_SMEM (5 * ATILE * 2)     // 174080 B

// ---------------------------------------------------------------------------
// Device scratch (all fp16 now; lo arrays pre-scaled by 2048)
// ---------------------------------------------------------------------------
__device__ __half g_xh[(size_t)MTOT * H_];   // x fp16 hi (also V-proj A operand)
__device__ __half g_xl[(size_t)MTOT * H_];   // x fp16 lo * 2048
__device__ __half g_wh[2ull * HH];           // Wq,Wk fp16 hi
__device__ __half g_wl[2ull * HH];           // Wq,Wk fp16 lo * 2048
__device__ __half g_wvf[HH];                 // Wv fp16
__device__ __half g_wof[HH];                 // Wo fp16
__device__ __half g_cf [(size_t)MTOT * H_];  // ctx fp16
__device__ __half g_qh[(size_t)MTOT * H_];   // q fp16 hi (post-RoPE)
__device__ __half g_ql[(size_t)MTOT * H_];   // q fp16 lo * 2048
__device__ __half g_kh[(size_t)MTOT * H_];
__device__ __half g_kl[(size_t)MTOT * H_];
__device__ __half g_vh[(size_t)MTOT * H_];   // v fp16 single

// ---------------------------------------------------------------------------
// PTX helpers
// ---------------------------------------------------------------------------
__device__ __forceinline__ uint32_t smem_u32(const void* p) {
    uint32_t a;
    asm("{ .reg .u64 t; cvta.to.shared.u64 t, %1; cvt.u32.u64 %0, t; }"
        : "=r"(a) : "l"(p));
    return a;
}

#define LDSM4(r, a) \
    asm volatile("ldmatrix.sync.aligned.m8n8.x4.shared.b16 {%0,%1,%2,%3}, [%4];" \
        : "=r"((r)[0]), "=r"((r)[1]), "=r"((r)[2]), "=r"((r)[3]) : "r"(a))
#define LDSM4T(r, a) \
    asm volatile("ldmatrix.sync.aligned.m8n8.x4.trans.shared.b16 {%0,%1,%2,%3}, [%4];" \
        : "=r"((r)[0]), "=r"((r)[1]), "=r"((r)[2]), "=r"((r)[3]) : "r"(a))

// fp16 inputs, fp32 accumulators
#define MMAH(d, a, b0v, b1v) \
    asm volatile("mma.sync.aligned.m16n8k16.row.col.f32.f16.f16.f32 " \
        "{%0,%1,%2,%3},{%4,%5,%6,%7},{%8,%9},{%0,%1,%2,%3};" \
        : "+f"((d)[0]), "+f"((d)[1]), "+f"((d)[2]), "+f"((d)[3]) \
        : "r"((a)[0]), "r"((a)[1]), "r"((a)[2]), "r"((a)[3]), \
          "r"(b0v), "r"(b1v))
// fp16 inputs, fp16 accumulators (correction terms)
#define MMAHF(d, a, b0v, b1v) \
    asm volatile("mma.sync.aligned.m16n8k16.row.col.f16.f16.f16.f16 " \
        "{%0,%1},{%2,%3,%4,%5},{%6,%7},{%0,%1};" \
        : "+r"((d)[0]), "+r"((d)[1]) \
        : "r"((a)[0]), "r"((a)[1]), "r"((a)[2]), "r"((a)[3]), \
          "r"(b0v), "r"(b1v))

#define CPA16(dst, src) \
    asm volatile("cp.async.cg.shared.global [%0], [%1], 16;" \
        :: "r"(dst), "l"(src) : "memory")
#define CPA_COMMIT() asm volatile("cp.async.commit_group;" ::: "memory")
#define CPA_WAIT1()  asm volatile("cp.async.wait_group 1;" ::: "memory")
#define CPA_WAIT0()  asm volatile("cp.async.wait_group 0;" ::: "memory")

// ---------------------------------------------------------------------------
// Prefetchers
// ---------------------------------------------------------------------------
__device__ __forceinline__ void prefetch4(
    uint32_t sdst, const char* s0, const char* s1,
    const char* s2, const char* s3, int kc)
{
    const char* srcs[4] = { s0, s1, s2, s3 };
    const int tid = threadIdx.x;
    #pragma unroll
    for (int it = 0; it < 8; it++) {
        int idx  = it * 256 + tid;
        int tile = idx >> 9;
        int r    = (idx >> 2) & 127;
        int cv   = idx & 3;
        const char* src = srcs[tile] + (size_t)r * (H_ * 2) + kc * (BK * 2) + cv * 16;
        uint32_t dst = sdst + tile * TILE_B + (uint32_t)(r * TSTRIDE + cv * 8) * 2;
        CPA16(dst, src);
    }
    CPA_COMMIT();
}

__device__ __forceinline__ void prefetch2(
    uint32_t sdst, const char* s0, const char* s1, int kc)
{
    const char* srcs[2] = { s0, s1 };
    const int tid = threadIdx.x;
    #pragma unroll
    for (int it = 0; it < 4; it++) {
        int idx  = it * 256 + tid;
        int tile = idx >> 9;
        int r    = (idx >> 2) & 127;
        int cv   = idx & 3;
        const char* src = srcs[tile] + (size_t)r * (H_ * 2) + kc * (BK * 2) + cv * 16;
        uint32_t dst = sdst + tile * TILE_B + (uint32_t)(r * TSTRIDE + cv * 8) * 2;
        CPA16(dst, src);
    }
    CPA_COMMIT();
}

// ---------------------------------------------------------------------------
// 3-term split-fp16 GEMM (Q,K projections): hh in f32-accum, cross terms in
// shared f16 accumulators (lo operands pre-scaled by 2048).
// ---------------------------------------------------------------------------
__device__ __forceinline__ void gemm_mainqk(
    const __half* __restrict__ Ah, const __half* __restrict__ Al,
    const __half* __restrict__ Wh, const __half* __restrict__ Wl,
    int m0, int n0, float acc[2][8][4])
{
    extern __shared__ char smx[];
    const uint32_t sbase = smem_u32(smx);
    const char* a0 = (const char*)(Ah + (size_t)m0 * H_);
    const char* a1 = (const char*)(Al + (size_t)m0 * H_);
    const char* b0 = (const char*)(Wh + (size_t)n0 * H_);
    const char* b1 = (const char*)(Wl + (size_t)n0 * H_);
    const int lane = threadIdx.x & 31;
    const int warp = threadIdx.x >> 5;
    const int wm = warp & 3;
    const int wn = warp >> 2;
    const int lrow = lane & 15;
    const int lk8  = (lane >> 4) * 8;

    uint32_t cacc[2][8][2];
    #pragma unroll
    for (int g = 0; g < 2; g++)
        #pragma unroll
        for (int j = 0; j < 8; j++) { cacc[g][j][0] = 0; cacc[g][j][1] = 0; }

    prefetch4(sbase, a0, a1, b0, b1, 0);

    for (int c = 0; c < NCH; c++) {
        const uint32_t sbuf = sbase + (uint32_t)(c & 1) * BUF_B;
        if (c + 1 < NCH) {
            prefetch4(sbase + (uint32_t)((c + 1) & 1) * BUF_B, a0, a1, b0, b1, c + 1);
            CPA_WAIT1();
        } else {
            CPA_WAIT0();
        }
        __syncthreads();

        #pragma unroll
        for (int ks = 0; ks < 2; ks++) {
            const int koff = ks * 16 + lk8;
            uint32_t ah[2][4], al[2][4];
            #pragma unroll
            for (int g = 0; g < 2; g++) {
                uint32_t addr = sbuf +
                    (uint32_t)((wm * 32 + g * 16 + lrow) * TSTRIDE + koff) * 2;
                LDSM4(ah[g], addr);
                LDSM4(al[g], addr + TILE_B);
            }
            #pragma unroll
            for (int nb = 0; nb < 4; nb++) {
                uint32_t addr = sbuf + 2 * TILE_B +
                    (uint32_t)((wn * 64 + nb * 16 + lrow) * TSTRIDE + koff) * 2;
                uint32_t bh[4], bl[4];
                LDSM4(bh, addr);
                LDSM4(bl, addr + TILE_B);
                // main hh term, fp32 accum
                MMAH(acc[0][2*nb],   ah[0], bh[0], bh[2]);
                MMAH(acc[0][2*nb+1], ah[0], bh[1], bh[3]);
                MMAH(acc[1][2*nb],   ah[1], bh[0], bh[2]);
                MMAH(acc[1][2*nb+1], ah[1], bh[1], bh[3]);
                // cross terms, fp16 accum (scaled lo operands)
                MMAHF(cacc[0][2*nb],   ah[0], bl[0], bl[2]);
                MMAHF(cacc[0][2*nb+1], ah[0], bl[1], bl[3]);
                MMAHF(cacc[1][2*nb],   ah[1], bl[0], bl[2]);
                MMAHF(cacc[1][2*nb+1], ah[1], bl[1], bl[3]);

                MMAHF(cacc[0][2*nb],   al[0], bh[0], bh[2]);
                MMAHF(cacc[0][2*nb+1], al[0], bh[1], bh[3]);
                MMAHF(cacc[1][2*nb],   al[1], bh[0], bh[2]);
                MMAHF(cacc[1][2*nb+1], al[1], bh[1], bh[3]);
            }
        }
        __syncthreads();
    }

    // fold scaled corrections into fp32 accumulators
    #pragma unroll
    for (int g = 0; g < 2; g++)
        #pragma unroll
        for (int j = 0; j < 8; j++) {
            __half2 c0 = *(__half2*)&cacc[g][j][0];
            __half2 c1 = *(__half2*)&cacc[g][j][1];
            acc[g][j][0] += __low2float(c0)  * INVLO;
            acc[g][j][1] += __high2float(c0) * INVLO;
            acc[g][j][2] += __low2float(c1)  * INVLO;
            acc[g][j][3] += __high2float(c1) * INVLO;
        }
}

// ---------------------------------------------------------------------------
// 1-term fp16 GEMM (V projection, output projection)
// ---------------------------------------------------------------------------
__device__ __forceinline__ void gemm_main1(
    const __half* __restrict__ A, const __half* __restrict__ W,
    int m0, int n0, float acc[2][8][4])
{
    extern __shared__ char smx[];
    const uint32_t sbase = smem_u32(smx);
    const char* a0 = (const char*)(A + (size_t)m0 * H_);
    const char* b0 = (const char*)(W + (size_t)n0 * H_);
    const int lane = threadIdx.x & 31;
    const int warp = threadIdx.x >> 5;
    const int wm = warp & 3;
    const int wn = warp >> 2;
    const int lrow = lane & 15;
    const int lk8  = (lane >> 4) * 8;

    prefetch2(sbase, a0, b0, 0);

    for (int c = 0; c < NCH; c++) {
        const uint32_t sbuf = sbase + (uint32_t)(c & 1) * BUF1_B;
        if (c + 1 < NCH) {
            prefetch2(sbase + (uint32_t)((c + 1) & 1) * BUF1_B, a0, b0, c + 1);
            CPA_WAIT1();
        } else {
            CPA_WAIT0();
        }
        __syncthreads();

        #pragma unroll
        for (int ks = 0; ks < 2; ks++) {
            const int koff = ks * 16 + lk8;
            uint32_t ah[2][4];
            #pragma unroll
            for (int g = 0; g < 2; g++) {
                uint32_t addr = sbuf +
                    (uint32_t)((wm * 32 + g * 16 + lrow) * TSTRIDE + koff) * 2;
                LDSM4(ah[g], addr);
            }
            #pragma unroll
            for (int nb = 0; nb < 4; nb++) {
                uint32_t addr = sbuf + TILE_B +
                    (uint32_t)((wn * 64 + nb * 16 + lrow) * TSTRIDE + koff) * 2;
                uint32_t bh[4];
                LDSM4(bh, addr);
                MMAH(acc[0][2*nb],   ah[0], bh[0], bh[2]);
                MMAH(acc[0][2*nb+1], ah[0], bh[1], bh[3]);
                MMAH(acc[1][2*nb],   ah[1], bh[0], bh[2]);
                MMAH(acc[1][2*nb+1], ah[1], bh[1], bh[3]);
            }
        }
        __syncthreads();
    }
}

__device__ __forceinline__ void acc_to_smem(float acc[2][8][4], float* smf)
{
    const int lane = threadIdx.x & 31;
    const int warp = threadIdx.x >> 5;
    const int wm = warp & 3, wn = warp >> 2;
    #pragma unroll
    for (int g = 0; g < 2; g++) {
        #pragma unroll
        for (int j = 0; j < 8; j++) {
            int row = wm * 32 + g * 16 + (lane >> 2);
            int col = wn * 64 + (j >> 1) * 16 + (j & 1) * 8 + 2 * (lane & 3);
            smf[row * 132 + col]           = acc[g][j][0];
            smf[row * 132 + col + 1]       = acc[g][j][1];
            smf[(row + 8) * 132 + col]     = acc[g][j][2];
            smf[(row + 8) * 132 + col + 1] = acc[g][j][3];
        }
    }
}

// ---------------------------------------------------------------------------
// QKV projection. z<2: 3-term fp16 GEMM + RoPE -> q/k fp16 hi + lo*2048.
//                 z=2: 1-term fp16 GEMM        -> v fp16 single.
// ---------------------------------------------------------------------------
__global__ __launch_bounds__(256)
void qkv_mma_kernel(const float* __restrict__ cs, const float* __restrict__ sn)
{
    const int z    = blockIdx.z;
    const int head = blockIdx.x;
    const int m0   = blockIdx.y * 128;
    const int n0   = head * 128;

    float acc[2][8][4];
    #pragma unroll
    for (int g = 0; g < 2; g++)
        #pragma unroll
        for (int j = 0; j < 8; j++)
            #pragma unroll
            for (int e = 0; e < 4; e++) acc[g][j][e] = 0.f;

    if (z < 2) {
        gemm_mainqk(g_xh, g_xl, g_wh + (size_t)z * HH, g_wl + (size_t)z * HH,
                    m0, n0, acc);
    } else {
        gemm_main1(g_xh, g_wvf, m0, n0, acc);
    }

    extern __shared__ char smx[];
    float* smf = (float*)smx;
    acc_to_smem(acc, smf);
    __syncthreads();

    const int t  = threadIdx.x;
    const int r  = t >> 1;
    const int dh = (t & 1) * 32;
    const int m  = m0 + r;
    const int s  = m & (S_ - 1);
    const int b  = m >> 11;
    const size_t rowbase = ((size_t)(b * NH + head) * S_ + s) * HD;

    if (z < 2) {
        __half* dsth = ((z == 0) ? g_qh : g_kh) + rowbase;
        __half* dstl = ((z == 0) ? g_ql : g_kl) + rowbase;
        const float* crow = cs + (size_t)s * HD;
        const float* srow = sn + (size_t)s * HD;
        #pragma unroll
        for (int j = 0; j < 32; j++) {
            float lo = smf[r * 132 + dh + j];
            float hi = smf[r * 132 + dh + j + 64];
            float olo = lo * crow[dh + j]      - hi * srow[dh + j];
            float ohi = hi * crow[dh + j + 64] + lo * srow[dh + j + 64];
            __half a  = __float2half_rn(olo);
            __half bq = __float2half_rn(ohi);
            dsth[dh + j]      = a;
            dsth[dh + j + 64] = bq;
            dstl[dh + j]      = __float2half_rn((olo - __half2float(a)) * LOSCL);
            dstl[dh + j + 64] = __float2half_rn((ohi - __half2float(bq)) * LOSCL);
        }
    } else {
        __half* dst = g_vh + rowbase;
        #pragma unroll
        for (int j = 0; j < 32; j++) {
            dst[dh + j]      = __float2half_rn(smf[r * 132 + dh + j]);
            dst[dh + j + 64] = __float2half_rn(smf[r * 132 + dh + j + 64]);
        }
    }
}

// ---------------------------------------------------------------------------
// Output projection: out = ctx(fp16) @ Wo(fp16)^T, 1-term
// ---------------------------------------------------------------------------
__global__ __launch_bounds__(256, 2)
void outproj_mma_kernel(float* __restrict__ out)
{
    const int m0 = blockIdx.y * 128;
    const int n0 = blockIdx.x * 128;

    float acc[2][8][4];
    #pragma unroll
    for (int g = 0; g < 2; g++)
        #pragma unroll
        for (int j = 0; j < 8; j++)
            #pragma unroll
            for (int e = 0; e < 4; e++) acc[g][j][e] = 0.f;

    gemm_main1(g_cf, g_wof, m0, n0, acc);

    const int lane = threadIdx.x & 31;
    const int warp = threadIdx.x >> 5;
    const int wm = warp & 3, wn = warp >> 2;
    #pragma unroll
    for (int g = 0; g < 2; g++) {
        #pragma unroll
        for (int j = 0; j < 8; j++) {
            size_t row = (size_t)m0 + wm * 32 + g * 16 + (lane >> 2);
            int col = n0 + wn * 64 + (j >> 1) * 16 + (j & 1) * 8 + 2 * (lane & 3);
            *(float2*)&out[row * H_ + col] =
                make_float2(acc[g][j][0], acc[g][j][1]);
            *(float2*)&out[(row + 8) * H_ + col] =
                make_float2(acc[g][j][2], acc[g][j][3]);
        }
    }
}

// ---------------------------------------------------------------------------
// fp32 -> fp16 hi + (lo*2048) split; fp32 -> fp16 convert
// ---------------------------------------------------------------------------
__global__ void split16_kernel(const float* __restrict__ src,
                               __half* __restrict__ hi,
                               __half* __restrict__ lo, int n4)
{
    int i = blockIdx.x * blockDim.x + threadIdx.x;
    if (i >= n4) return;
    float4 v = ((const float4*)src)[i];
    __half h0 = __float2half_rn(v.x), h1 = __float2half_rn(v.y);
    __half h2 = __float2half_rn(v.z), h3 = __float2half_rn(v.w);
    __half l0 = __float2half_rn((v.x - __half2float(h0)) * LOSCL);
    __half l1 = __float2half_rn((v.y - __half2float(h1)) * LOSCL);
    __half l2 = __float2half_rn((v.z - __half2float(h2)) * LOSCL);
    __half l3 = __float2half_rn((v.w - __half2float(h3)) * LOSCL);
    ((__half2*)hi)[2*i]   = __halves2half2(h0, h1);
    ((__half2*)hi)[2*i+1] = __halves2half2(h2, h3);
    ((__half2*)lo)[2*i]   = __halves2half2(l0, l1);
    ((__half2*)lo)[2*i+1] = __halves2half2(l2, l3);
}

__global__ void cvt_kernel(const float* __restrict__ src,
                           __half* __restrict__ dst, int n4)
{
    int i = blockIdx.x * blockDim.x + threadIdx.x;
    if (i >= n4) return;
    float4 v = ((const float4*)src)[i];
    ((__half2*)dst)[2*i]   = __floats2half2_rn(v.x, v.y);
    ((__half2*)dst)[2*i+1] = __floats2half2_rn(v.z, v.w);
}

// ---------------------------------------------------------------------------
// Tensor-core causal flash attention.
//   S = Qh·Kh (f32 acc) + [Qh·Kl' + Ql'·Kh] (f16 acc, lo scaled) / 2048
//   O += P(fp16)·Vh (single product)
// ---------------------------------------------------------------------------
__global__ __launch_bounds__(256, 1)
void attn_mma_kernel()
{
    extern __shared__ char smem[];
    __half* sQh = (__half*)smem;
    __half* sQl = sQh + ATILE;
    __half* sKh = sQl + ATILE;
    __half* sKl = sKh + ATILE;
    __half* sVh = sKl + ATILE;

    const int tid  = threadIdx.x;
    const int lane = tid & 31;
    const int warp = tid >> 5;
    const int lrow = lane & 7;
    const int lq   = lane >> 3;
    const int qt   = (gridDim.x - 1) - blockIdx.x;
    const int bh   = blockIdx.y;
    const int q0   = qt * 128;
    const size_t base = (size_t)bh * S_ * HD;

    const uint32_t sQh_u = smem_u32(sQh);
    const uint32_t sQl_u = smem_u32(sQl);
    const uint32_t sKh_u = smem_u32(sKh);
    const uint32_t sKl_u = smem_u32(sKl);
    const uint32_t sVh_u = smem_u32(sVh);

    #pragma unroll
    for (int it = 0; it < 8; it++) {
        int idx = it * 256 + tid;
        int r   = idx >> 4;
        int c8  = (idx & 15) * 8;
        size_t g = base + (size_t)(q0 + r) * HD + c8;
        uint32_t so = (uint32_t)(r * AST + c8) * 2;
        CPA16(sQh_u + so, (const char*)&g_qh[g]);
        CPA16(sQl_u + so, (const char*)&g_ql[g]);
    }
    CPA_COMMIT();
    CPA_WAIT0();
    __syncthreads();

    const int qrow  = warp * 16 + ((lq & 1) ? 8 : 0) + lrow;
    const int qcolb = ((lq & 2) ? 8 : 0);

    uint32_t qfh[8][4];
    #pragma unroll
    for (int ks = 0; ks < 8; ks++)
        LDSM4(qfh[ks], sQh_u + (uint32_t)(qrow * AST + ks * 16 + qcolb) * 2);

    float o[16][4];
    #pragma unroll
    for (int j = 0; j < 16; j++)
        #pragma unroll
        for (int e = 0; e < 4; e++) o[j][e] = 0.f;
    float mr[2] = { -1e30f, -1e30f };
    float lr_[2] = { 0.f, 0.f };

    const int krow_b = ((lq & 2) ? 8 : 0) + lrow;
    const int kcol_b = ((lq & 1) ? 8 : 0);
    const int vrow_b = ((lq & 1) ? 8 : 0) + lrow;
    const int vcol_b = ((lq & 2) ? 8 : 0);
    const int myrow  = lane >> 2;
    const int mycol  = 2 * (lane & 3);

    for (int kt = 0; kt <= qt; kt++) {
        const int kb = kt * 128;
        __syncthreads();

        #pragma unroll
        for (int it = 0; it < 8; it++) {
            int idx = it * 256 + tid;
            int r   = idx >> 4;
            int c8  = (idx & 15) * 8;
            size_t g = base + (size_t)(kb + r) * HD + c8;
            uint32_t so = (uint32_t)(r * AST + c8) * 2;
            CPA16(sKh_u + so, (const char*)&g_kh[g]);
            CPA16(sKl_u + so, (const char*)&g_kl[g]);
            CPA16(sVh_u + so, (const char*)&g_vh[g]);
        }
        CPA_COMMIT();
        CPA_WAIT0();
        __syncthreads();

        // ---- S: hh into f32, cross terms into f16 accumulators ----
        float sf[16][4];
        #pragma unroll
        for (int j = 0; j < 16; j++)
            #pragma unroll
            for (int e = 0; e < 4; e++) sf[j][e] = 0.f;

        uint32_t cacc[8][2][2];
        #pragma unroll
        for (int j = 0; j < 8; j++) {
            cacc[j][0][0] = 0; cacc[j][0][1] = 0;
            cacc[j][1][0] = 0; cacc[j][1][1] = 0;
        }

        #pragma unroll
        for (int ks = 0; ks < 8; ks++) {
            uint32_t qfl[4];
            LDSM4(qfl, sQl_u + (uint32_t)(qrow * AST + ks * 16 + qcolb) * 2);
            #pragma unroll
            for (int jj = 0; jj < 8; jj += 2) {
                int col = ks * 16 + kcol_b;
                uint32_t so0 = (uint32_t)(((jj    ) * 16 + krow_b) * AST + col) * 2;
                uint32_t so1 = (uint32_t)(((jj + 1) * 16 + krow_b) * AST + col) * 2;
                uint32_t kfh0[4], kfl0[4], kfh1[4], kfl1[4];
                LDSM4(kfh0, sKh_u + so0);
                LDSM4(kfh1, sKh_u + so1);
                LDSM4(kfl0, sKl_u + so0);
                LDSM4(kfl1, sKl_u + so1);
                // hh (f32 accum)
                MMAH(sf[2*jj],   qfh[ks], kfh0[0], kfh0[1]);
                MMAH(sf[2*jj+1], qfh[ks], kfh0[2], kfh0[3]);
                MMAH(sf[2*jj+2], qfh[ks], kfh1[0], kfh1[1]);
                MMAH(sf[2*jj+3], qfh[ks], kfh1[2], kfh1[3]);
                // hl (f16 accum)
                MMAHF(cacc[jj][0],   qfh[ks], kfl0[0], kfl0[1]);
                MMAHF(cacc[jj][1],   qfh[ks], kfl0[2], kfl0[3]);
                MMAHF(cacc[jj+1][0], qfh[ks], kfl1[0], kfl1[1]);
                MMAHF(cacc[jj+1][1], qfh[ks], kfl1[2], kfl1[3]);
                // lh (f16 accum)
                MMAHF(cacc[jj][0],   qfl, kfh0[0], kfh0[1]);
                MMAHF(cacc[jj][1],   qfl, kfh0[2], kfh0[3]);
                MMAHF(cacc[jj+1][0], qfl, kfh1[0], kfh1[1]);
                MMAHF(cacc[jj+1][1], qfl, kfh1[2], kfh1[3]);
            }
        }

        // fold scaled corrections
        #pragma unroll
        for (int jj = 0; jj < 8; jj++)
            #pragma unroll
            for (int h2 = 0; h2 < 2; h2++) {
                __half2 c0 = *(__half2*)&cacc[jj][h2][0];
                __half2 c1 = *(__half2*)&cacc[jj][h2][1];
                sf[2*jj+h2][0] += __low2float(c0)  * INVLO;
                sf[2*jj+h2][1] += __high2float(c0) * INVLO;
                sf[2*jj+h2][2] += __low2float(c1)  * INVLO;
                sf[2*jj+h2][3] += __high2float(c1) * INVLO;
            }

        // ---- online softmax ----
        const bool diag = (kt == qt);
        const int grow0 = q0 + warp * 16 + myrow;
        #pragma unroll
        for (int rr = 0; rr < 2; rr++) {
            const int grow = grow0 + rr * 8;
            float mx = -1e30f;
            #pragma unroll
            for (int j = 0; j < 16; j++) {
                #pragma unroll
                for (int e = 0; e < 2; e++) {
                    float v = sf[j][rr * 2 + e] * SCALE;
                    if (diag && (kb + j * 8 + mycol + e) > grow) v = -1e30f;
                    sf[j][rr * 2 + e] = v;
                    mx = fmaxf(mx, v);
                }
            }
            mx = fmaxf(mx, __shfl_xor_sync(0xffffffffu, mx, 1));
            mx = fmaxf(mx, __shfl_xor_sync(0xffffffffu, mx, 2));
            float mnew  = fmaxf(mr[rr], mx);
            float alpha = __expf(mr[rr] - mnew);
            mr[rr] = mnew;
            float ls = 0.f;
            #pragma unroll
            for (int j = 0; j < 16; j++) {
                #pragma unroll
                for (int e = 0; e < 2; e++) {
                    float p = __expf(sf[j][rr * 2 + e] - mnew);
                    sf[j][rr * 2 + e] = p;
                    ls += p;
                }
            }
            ls += __shfl_xor_sync(0xffffffffu, ls, 1);
            ls += __shfl_xor_sync(0xffffffffu, ls, 2);
            lr_[rr] = lr_[rr] * alpha + ls;
            #pragma unroll
            for (int j = 0; j < 16; j++) {
                o[j][rr * 2]     *= alpha;
                o[j][rr * 2 + 1] *= alpha;
            }
        }

        // ---- pack P to fp16 A-frags ----
        uint32_t pf[8][4];
        #pragma unroll
        for (int j = 0; j < 8; j++) {
            __half2 h;
            h = __floats2half2_rn(sf[2*j][0],   sf[2*j][1]);   pf[j][0] = *(uint32_t*)&h;
            h = __floats2half2_rn(sf[2*j][2],   sf[2*j][3]);   pf[j][1] = *(uint32_t*)&h;
            h = __floats2half2_rn(sf[2*j+1][0], sf[2*j+1][1]); pf[j][2] = *(uint32_t*)&h;
            h = __floats2half2_rn(sf[2*j+1][2], sf[2*j+1][3]); pf[j][3] = *(uint32_t*)&h;
        }

        // ---- O += P · Vh ----
        #pragma unroll
        for (int j = 0; j < 8; j++) {
            int row = j * 16 + vrow_b;
            #pragma unroll
            for (int dd = 0; dd < 8; dd += 2) {
                uint32_t so0 = (uint32_t)(row * AST + (dd    ) * 16 + vcol_b) * 2;
                uint32_t so1 = (uint32_t)(row * AST + (dd + 1) * 16 + vcol_b) * 2;
                uint32_t vh0[4], vh1[4];
                LDSM4T(vh0, sVh_u + so0);
                LDSM4T(vh1, sVh_u + so1);
                MMAH(o[2*dd],   pf[j], vh0[0], vh0[1]);
                MMAH(o[2*dd+1], pf[j], vh0[2], vh0[3]);
                MMAH(o[2*dd+2], pf[j], vh1[0], vh1[1]);
                MMAH(o[2*dd+3], pf[j], vh1[2], vh1[3]);
            }
        }
    }

    // ---- epilogue: normalize, write ctx fp16 ----
    const int b = bh >> 4;
    const int h = bh & 15;
    float inv0 = 1.0f / lr_[0];
    float inv1 = 1.0f / lr_[1];
    const int srow = q0 + warp * 16 + myrow;
    #pragma unroll
    for (int j = 0; j < 16; j++) {
        int col = j * 8 + mycol;
        #pragma unroll
        for (int rr = 0; rr < 2; rr++) {
            float v0 = o[j][rr * 2]     * (rr ? inv1 : inv0);
            float v1 = o[j][rr * 2 + 1] * (rr ? inv1 : inv0);
            size_t off = ((size_t)(b * S_) + srow + rr * 8) * H_ + h * HD + col;
            *(__half2*)&g_cf[off] = __floats2half2_rn(v0, v1);
        }
    }
}

// ---------------------------------------------------------------------------
extern "C" void kernel_launch(void* const* d_in, const int* in_sizes, int n_in,
                              void* d_out, int out_size)
{
    (void)in_sizes; (void)n_in; (void)out_size;
    const float* x  = (const float*)d_in[0];
    const float* Wq = (const float*)d_in[1];
    const float* Wk = (const float*)d_in[2];
    const float* Wv = (const float*)d_in[3];
    const float* Wo = (const float*)d_in[4];
    const float* cs = (const float*)d_in[5];
    const float* sn = (const float*)d_in[6];
    float* out = (float*)d_out;

    void *pxh, *pxl, *pwh, *pwl, *pwvf, *pwof;
    cudaGetSymbolAddress(&pxh, g_xh);
    cudaGetSymbolAddress(&pxl, g_xl);
    cudaGetSymbolAddress(&pwh, g_wh);
    cudaGetSymbolAddress(&pwl, g_wl);
    cudaGetSymbolAddress(&pwvf, g_wvf);
    cudaGetSymbolAddress(&pwof, g_wof);

    {
        int n4 = MTOT * H_ / 4;
        int w4 = H_ * H_ / 4;
        split16_kernel<<<(n4 + 255) / 256, 256>>>(x, (__half*)pxh,
                                                  (__half*)pxl, n4);
        split16_kernel<<<(w4 + 255) / 256, 256>>>(Wq, (__half*)pwh,
                                                  (__half*)pwl, w4);
        split16_kernel<<<(w4 + 255) / 256, 256>>>(Wk, (__half*)pwh + HH,
                                                  (__half*)pwl + HH, w4);
        cvt_kernel<<<(w4 + 255) / 256, 256>>>(Wv, (__half*)pwvf, w4);
        cvt_kernel<<<(w4 + 255) / 256, 256>>>(Wo, (__half*)pwof, w4);
    }

    cudaFuncSetAttribute(qkv_mma_kernel,
                         cudaFuncAttributeMaxDynamicSharedMemorySize, GEMM_SMEM);
    qkv_mma_kernel<<<dim3(H_ / 128, MTOT / 128, 3), 256, GEMM_SMEM>>>(cs, sn);

    cudaFuncSetAttribute(attn_mma_kernel,
                         cudaFuncAttributeMaxDynamicSharedMemorySize, ATTN_SMEM);
    attn_mma_kernel<<<dim3(S_ / 128, B_ * NH), 256, ATTN_SMEM>>>();

    cudaFuncSetAttribute(outproj_mma_kernel,
                         cudaFuncAttributeMaxDynamicSharedMemorySize, OUT_SMEM);
    outproj_mma_kernel<<<dim3(H_ / 128, MTOT / 128), 256, OUT_SMEM>>>(out);
}

// round 9
// speedup vs baseline: 1.1104x; 1.1104x over previous
#include <cuda_runtime.h>
#include <cuda_bf16.h>
#include <cuda_fp16.h>
#include <cstdint>

#define B_    2
#define S_    2048
#define H_    2048
#define NH    16
#define HD    128
#define MTOT  (B_ * S_)           // 4096
#define SCALE 11.313708498984761f // sqrt(128)
#define HH    ((size_t)H_ * H_)

// GEMM tiling
#define BK      32
#define NCH     (H_ / BK)
#define TSTRIDE 40
#define TILE_B  (128 * TSTRIDE * 2)   // 10240 B
#define BUF_B   (4 * TILE_B)          // 3-term: Ah,Al,Wh,Wl
#define BUF1_B  (2 * TILE_B)          // 1-term: A,W
#define GEMM_SMEM (2 * BUF_B)         // 81920 B
#define OUT_SMEM  (2 * BUF1_B)        // 40960 B

// Attention smem: 6 half tiles [128][136]: 2 buffers x {Kh,Kl,Vh}
#define AST 136
#define ATILE  (128 * AST)            // halves per tile
#define ATILE2 (ATILE * 2)            // bytes per tile
#define ATTN_SMEM (6 * ATILE2)        // 208896 B

// ---------------------------------------------------------------------------
// Device scratch
// ---------------------------------------------------------------------------
__device__ __nv_bfloat16 g_xh[(size_t)MTOT * H_];   // x bf16 hi/lo (Q,K proj)
__device__ __nv_bfloat16 g_xl[(size_t)MTOT * H_];
__device__ __nv_bfloat16 g_wh[2ull * HH];           // Wq,Wk bf16 hi/lo
__device__ __nv_bfloat16 g_wl[2ull * HH];
__device__ __half g_xf [(size_t)MTOT * H_];         // x fp16 (V proj)
__device__ __half g_wvf[HH];                        // Wv fp16
__device__ __half g_wof[HH];                        // Wo fp16
__device__ __half g_cf [(size_t)MTOT * H_];         // ctx fp16
__device__ __half g_qh[(size_t)MTOT * H_];          // q fp16 hi/lo (post-RoPE)
__device__ __half g_ql[(size_t)MTOT * H_];
__device__ __half g_kh[(size_t)MTOT * H_];
__device__ __half g_kl[(size_t)MTOT * H_];
__device__ __half g_vh[(size_t)MTOT * H_];          // v fp16 single

// ---------------------------------------------------------------------------
// PTX helpers
// ---------------------------------------------------------------------------
__device__ __forceinline__ uint32_t smem_u32(const void* p) {
    uint32_t a;
    asm("{ .reg .u64 t; cvta.to.shared.u64 t, %1; cvt.u32.u64 %0, t; }"
        : "=r"(a) : "l"(p));
    return a;
}

#define LDSM4(r, a) \
    asm volatile("ldmatrix.sync.aligned.m8n8.x4.shared.b16 {%0,%1,%2,%3}, [%4];" \
        : "=r"((r)[0]), "=r"((r)[1]), "=r"((r)[2]), "=r"((r)[3]) : "r"(a))
#define LDSM4T(r, a) \
    asm volatile("ldmatrix.sync.aligned.m8n8.x4.trans.shared.b16 {%0,%1,%2,%3}, [%4];" \
        : "=r"((r)[0]), "=r"((r)[1]), "=r"((r)[2]), "=r"((r)[3]) : "r"(a))

#define MMAB(d, a, b0v, b1v) \
    asm volatile("mma.sync.aligned.m16n8k16.row.col.f32.bf16.bf16.f32 " \
        "{%0,%1,%2,%3},{%4,%5,%6,%7},{%8,%9},{%0,%1,%2,%3};" \
        : "+f"((d)[0]), "+f"((d)[1]), "+f"((d)[2]), "+f"((d)[3]) \
        : "r"((a)[0]), "r"((a)[1]), "r"((a)[2]), "r"((a)[3]), \
          "r"(b0v), "r"(b1v))
#define MMAH(d, a, b0v, b1v) \
    asm volatile("mma.sync.aligned.m16n8k16.row.col.f32.f16.f16.f32 " \
        "{%0,%1,%2,%3},{%4,%5,%6,%7},{%8,%9},{%0,%1,%2,%3};" \
        : "+f"((d)[0]), "+f"((d)[1]), "+f"((d)[2]), "+f"((d)[3]) \
        : "r"((a)[0]), "r"((a)[1]), "r"((a)[2]), "r"((a)[3]), \
          "r"(b0v), "r"(b1v))

#define CPA16(dst, src) \
    asm volatile("cp.async.cg.shared.global [%0], [%1], 16;" \
        :: "r"(dst), "l"(src) : "memory")
#define CPA_COMMIT() asm volatile("cp.async.commit_group;" ::: "memory")
#define CPA_WAIT1()  asm volatile("cp.async.wait_group 1;" ::: "memory")
#define CPA_WAIT0()  asm volatile("cp.async.wait_group 0;" ::: "memory")

// ---------------------------------------------------------------------------
// 3-term split-bf16 GEMM (Q,K projections) — R7 version
// ---------------------------------------------------------------------------
__device__ __forceinline__ void prefetch4(
    uint32_t sdst, const char* s0, const char* s1,
    const char* s2, const char* s3, int kc)
{
    const char* srcs[4] = { s0, s1, s2, s3 };
    const int tid = threadIdx.x;
    #pragma unroll
    for (int it = 0; it < 8; it++) {
        int idx  = it * 256 + tid;
        int tile = idx >> 9;
        int r    = (idx >> 2) & 127;
        int cv   = idx & 3;
        const char* src = srcs[tile] + (size_t)r * (H_ * 2) + kc * (BK * 2) + cv * 16;
        uint32_t dst = sdst + tile * TILE_B + (uint32_t)(r * TSTRIDE + cv * 8) * 2;
        CPA16(dst, src);
    }
    CPA_COMMIT();
}

__device__ __forceinline__ void gemm_main3(
    const __nv_bfloat16* __restrict__ Ah, const __nv_bfloat16* __restrict__ Al,
    const __nv_bfloat16* __restrict__ Wh, const __nv_bfloat16* __restrict__ Wl,
    int m0, int n0, float acc[2][8][4])
{
    extern __shared__ char smx[];
    const uint32_t sbase = smem_u32(smx);
    const char* a0 = (const char*)(Ah + (size_t)m0 * H_);
    const char* a1 = (const char*)(Al + (size_t)m0 * H_);
    const char* b0 = (const char*)(Wh + (size_t)n0 * H_);
    const char* b1 = (const char*)(Wl + (size_t)n0 * H_);
    const int lane = threadIdx.x & 31;
    const int warp = threadIdx.x >> 5;
    const int wm = warp & 3;
    const int wn = warp >> 2;
    const int lrow = lane & 15;
    const int lk8  = (lane >> 4) * 8;

    prefetch4(sbase, a0, a1, b0, b1, 0);

    for (int c = 0; c < NCH; c++) {
        const uint32_t sbuf = sbase + (uint32_t)(c & 1) * BUF_B;
        if (c + 1 < NCH) {
            prefetch4(sbase + (uint32_t)((c + 1) & 1) * BUF_B, a0, a1, b0, b1, c + 1);
            CPA_WAIT1();
        } else {
            CPA_WAIT0();
        }
        __syncthreads();

        #pragma unroll
        for (int ks = 0; ks < 2; ks++) {
            const int koff = ks * 16 + lk8;
            uint32_t ah[2][4], al[2][4];
            #pragma unroll
            for (int g = 0; g < 2; g++) {
                uint32_t addr = sbuf +
                    (uint32_t)((wm * 32 + g * 16 + lrow) * TSTRIDE + koff) * 2;
                LDSM4(ah[g], addr);
                LDSM4(al[g], addr + TILE_B);
            }
            #pragma unroll
            for (int nb = 0; nb < 4; nb++) {
                uint32_t addr = sbuf + 2 * TILE_B +
                    (uint32_t)((wn * 64 + nb * 16 + lrow) * TSTRIDE + koff) * 2;
                uint32_t bh[4], bl[4];
                LDSM4(bh, addr);
                LDSM4(bl, addr + TILE_B);
                MMAB(acc[0][2*nb],   ah[0], bh[0], bh[2]);
                MMAB(acc[0][2*nb+1], ah[0], bh[1], bh[3]);
                MMAB(acc[1][2*nb],   ah[1], bh[0], bh[2]);
                MMAB(acc[1][2*nb+1], ah[1], bh[1], bh[3]);

                MMAB(acc[0][2*nb],   ah[0], bl[0], bl[2]);
                MMAB(acc[0][2*nb+1], ah[0], bl[1], bl[3]);
                MMAB(acc[1][2*nb],   ah[1], bl[0], bl[2]);
                MMAB(acc[1][2*nb+1], ah[1], bl[1], bl[3]);

                MMAB(acc[0][2*nb],   al[0], bh[0], bh[2]);
                MMAB(acc[0][2*nb+1], al[0], bh[1], bh[3]);
                MMAB(acc[1][2*nb],   al[1], bh[0], bh[2]);
                MMAB(acc[1][2*nb+1], al[1], bh[1], bh[3]);
            }
        }
        __syncthreads();
    }
}

// ---------------------------------------------------------------------------
// 1-term fp16 GEMM (V projection, output projection) — R7 version
// ---------------------------------------------------------------------------
__device__ __forceinline__ void prefetch2(
    uint32_t sdst, const char* s0, const char* s1, int kc)
{
    const char* srcs[2] = { s0, s1 };
    const int tid = threadIdx.x;
    #pragma unroll
    for (int it = 0; it < 4; it++) {
        int idx  = it * 256 + tid;
        int tile = idx >> 9;
        int r    = (idx >> 2) & 127;
        int cv   = idx & 3;
        const char* src = srcs[tile] + (size_t)r * (H_ * 2) + kc * (BK * 2) + cv * 16;
        uint32_t dst = sdst + tile * TILE_B + (uint32_t)(r * TSTRIDE + cv * 8) * 2;
        CPA16(dst, src);
    }
    CPA_COMMIT();
}

__device__ __forceinline__ void gemm_main1(
    const __half* __restrict__ A, const __half* __restrict__ W,
    int m0, int n0, float acc[2][8][4])
{
    extern __shared__ char smx[];
    const uint32_t sbase = smem_u32(smx);
    const char* a0 = (const char*)(A + (size_t)m0 * H_);
    const char* b0 = (const char*)(W + (size_t)n0 * H_);
    const int lane = threadIdx.x & 31;
    const int warp = threadIdx.x >> 5;
    const int wm = warp & 3;
    const int wn = warp >> 2;
    const int lrow = lane & 15;
    const int lk8  = (lane >> 4) * 8;

    prefetch2(sbase, a0, b0, 0);

    for (int c = 0; c < NCH; c++) {
        const uint32_t sbuf = sbase + (uint32_t)(c & 1) * BUF1_B;
        if (c + 1 < NCH) {
            prefetch2(sbase + (uint32_t)((c + 1) & 1) * BUF1_B, a0, b0, c + 1);
            CPA_WAIT1();
        } else {
            CPA_WAIT0();
        }
        __syncthreads();

        #pragma unroll
        for (int ks = 0; ks < 2; ks++) {
            const int koff = ks * 16 + lk8;
            uint32_t ah[2][4];
            #pragma unroll
            for (int g = 0; g < 2; g++) {
                uint32_t addr = sbuf +
                    (uint32_t)((wm * 32 + g * 16 + lrow) * TSTRIDE + koff) * 2;
                LDSM4(ah[g], addr);
            }
            #pragma unroll
            for (int nb = 0; nb < 4; nb++) {
                uint32_t addr = sbuf + TILE_B +
                    (uint32_t)((wn * 64 + nb * 16 + lrow) * TSTRIDE + koff) * 2;
                uint32_t bh[4];
                LDSM4(bh, addr);
                MMAH(acc[0][2*nb],   ah[0], bh[0], bh[2]);
                MMAH(acc[0][2*nb+1], ah[0], bh[1], bh[3]);
                MMAH(acc[1][2*nb],   ah[1], bh[0], bh[2]);
                MMAH(acc[1][2*nb+1], ah[1], bh[1], bh[3]);
            }
        }
        __syncthreads();
    }
}

__device__ __forceinline__ void acc_to_smem(float acc[2][8][4], float* smf)
{
    const int lane = threadIdx.x & 31;
    const int warp = threadIdx.x >> 5;
    const int wm = warp & 3, wn = warp >> 2;
    #pragma unroll
    for (int g = 0; g < 2; g++) {
        #pragma unroll
        for (int j = 0; j < 8; j++) {
            int row = wm * 32 + g * 16 + (lane >> 2);
            int col = wn * 64 + (j >> 1) * 16 + (j & 1) * 8 + 2 * (lane & 3);
            smf[row * 132 + col]           = acc[g][j][0];
            smf[row * 132 + col + 1]       = acc[g][j][1];
            smf[(row + 8) * 132 + col]     = acc[g][j][2];
            smf[(row + 8) * 132 + col + 1] = acc[g][j][3];
        }
    }
}

// ---------------------------------------------------------------------------
// QKV projection. z<2: 3-term bf16 GEMM + RoPE -> q/k fp16 hi/lo.
//                 z=2: 1-term fp16 GEMM       -> v fp16 single.
// ---------------------------------------------------------------------------
__global__ __launch_bounds__(256, 2)
void qkv_mma_kernel(const float* __restrict__ cs, const float* __restrict__ sn)
{
    const int z    = blockIdx.z;
    const int head = blockIdx.x;
    const int m0   = blockIdx.y * 128;
    const int n0   = head * 128;

    float acc[2][8][4];
    #pragma unroll
    for (int g = 0; g < 2; g++)
        #pragma unroll
        for (int j = 0; j < 8; j++)
            #pragma unroll
            for (int e = 0; e < 4; e++) acc[g][j][e] = 0.f;

    if (z < 2) {
        gemm_main3(g_xh, g_xl, g_wh + (size_t)z * HH, g_wl + (size_t)z * HH,
                   m0, n0, acc);
    } else {
        gemm_main1(g_xf, g_wvf, m0, n0, acc);
    }

    extern __shared__ char smx[];
    float* smf = (float*)smx;
    acc_to_smem(acc, smf);
    __syncthreads();

    const int t  = threadIdx.x;
    const int r  = t >> 1;
    const int dh = (t & 1) * 32;
    const int m  = m0 + r;
    const int s  = m & (S_ - 1);
    const int b  = m >> 11;
    const size_t rowbase = ((size_t)(b * NH + head) * S_ + s) * HD;

    if (z < 2) {
        __half* dsth = ((z == 0) ? g_qh : g_kh) + rowbase;
        __half* dstl = ((z == 0) ? g_ql : g_kl) + rowbase;
        const float* crow = cs + (size_t)s * HD;
        const float* srow = sn + (size_t)s * HD;
        #pragma unroll
        for (int j = 0; j < 32; j++) {
            float lo = smf[r * 132 + dh + j];
            float hi = smf[r * 132 + dh + j + 64];
            float olo = lo * crow[dh + j]      - hi * srow[dh + j];
            float ohi = hi * crow[dh + j + 64] + lo * srow[dh + j + 64];
            __half a  = __float2half_rn(olo);
            __half bq = __float2half_rn(ohi);
            dsth[dh + j]      = a;
            dsth[dh + j + 64] = bq;
            dstl[dh + j]      = __float2half_rn(olo - __half2float(a));
            dstl[dh + j + 64] = __float2half_rn(ohi - __half2float(bq));
        }
    } else {
        __half* dst = g_vh + rowbase;
        #pragma unroll
        for (int j = 0; j < 32; j++) {
            dst[dh + j]      = __float2half_rn(smf[r * 132 + dh + j]);
            dst[dh + j + 64] = __float2half_rn(smf[r * 132 + dh + j + 64]);
        }
    }
}

// ---------------------------------------------------------------------------
// Output projection: out = ctx(fp16) @ Wo(fp16)^T, 1-term
// ---------------------------------------------------------------------------
__global__ __launch_bounds__(256, 2)
void outproj_mma_kernel(float* __restrict__ out)
{
    const int m0 = blockIdx.y * 128;
    const int n0 = blockIdx.x * 128;

    float acc[2][8][4];
    #pragma unroll
    for (int g = 0; g < 2; g++)
        #pragma unroll
        for (int j = 0; j < 8; j++)
            #pragma unroll
            for (int e = 0; e < 4; e++) acc[g][j][e] = 0.f;

    gemm_main1(g_cf, g_wof, m0, n0, acc);

    const int lane = threadIdx.x & 31;
    const int warp = threadIdx.x >> 5;
    const int wm = warp & 3, wn = warp >> 2;
    #pragma unroll
    for (int g = 0; g < 2; g++) {
        #pragma unroll
        for (int j = 0; j < 8; j++) {
            size_t row = (size_t)m0 + wm * 32 + g * 16 + (lane >> 2);
            int col = n0 + wn * 64 + (j >> 1) * 16 + (j & 1) * 8 + 2 * (lane & 3);
            *(float2*)&out[row * H_ + col] =
                make_float2(acc[g][j][0], acc[g][j][1]);
            *(float2*)&out[(row + 8) * H_ + col] =
                make_float2(acc[g][j][2], acc[g][j][3]);
        }
    }
}

// ---------------------------------------------------------------------------
// fp32 -> bf16 hi/lo split; fp32 -> fp16 convert
// ---------------------------------------------------------------------------
__global__ void split_kernel(const float* __restrict__ src,
                             __nv_bfloat16* __restrict__ hi,
                             __nv_bfloat16* __restrict__ lo, int n4)
{
    int i = blockIdx.x * blockDim.x + threadIdx.x;
    if (i >= n4) return;
    float4 v = ((const float4*)src)[i];
    __nv_bfloat16 h0 = __float2bfloat16(v.x), h1 = __float2bfloat16(v.y);
    __nv_bfloat16 h2 = __float2bfloat16(v.z), h3 = __float2bfloat16(v.w);
    __nv_bfloat16 l0 = __float2bfloat16(v.x - __bfloat162float(h0));
    __nv_bfloat16 l1 = __float2bfloat16(v.y - __bfloat162float(h1));
    __nv_bfloat16 l2 = __float2bfloat16(v.z - __bfloat162float(h2));
    __nv_bfloat16 l3 = __float2bfloat16(v.w - __bfloat162float(h3));
    ((__nv_bfloat162*)hi)[2*i]   = __nv_bfloat162(h0, h1);
    ((__nv_bfloat162*)hi)[2*i+1] = __nv_bfloat162(h2, h3);
    ((__nv_bfloat162*)lo)[2*i]   = __nv_bfloat162(l0, l1);
    ((__nv_bfloat162*)lo)[2*i+1] = __nv_bfloat162(l2, l3);
}

__global__ void cvt_kernel(const float* __restrict__ src,
                           __half* __restrict__ dst, int n4)
{
    int i = blockIdx.x * blockDim.x + threadIdx.x;
    if (i >= n4) return;
    float4 v = ((const float4*)src)[i];
    ((__half2*)dst)[2*i]   = __floats2half2_rn(v.x, v.y);
    ((__half2*)dst)[2*i+1] = __floats2half2_rn(v.z, v.w);
}

// ---------------------------------------------------------------------------
// Tensor-core causal flash attention (split-fp16 QK^T, single-fp16 PV),
// double-buffered K/Kl/V tiles (Q smem recycled after fragment extraction).
// ---------------------------------------------------------------------------
__global__ __launch_bounds__(256, 1)
void attn_mma_kernel()
{
    extern __shared__ char smem[];
    const uint32_t sbase = smem_u32(smem);

    const int tid  = threadIdx.x;
    const int lane = tid & 31;
    const int warp = tid >> 5;
    const int lrow = lane & 7;
    const int lq   = lane >> 3;
    const int qt   = (gridDim.x - 1) - blockIdx.x;
    const int bh   = blockIdx.y;
    const int q0   = qt * 128;
    const size_t base = (size_t)bh * S_ * HD;

    // ---- Q prologue: load into tiles 0,1, extract fragments ----
    #pragma unroll
    for (int it = 0; it < 8; it++) {
        int idx = it * 256 + tid;
        int r   = idx >> 4;
        int c8  = (idx & 15) * 8;
        size_t g = base + (size_t)(q0 + r) * HD + c8;
        uint32_t so = (uint32_t)(r * AST + c8) * 2;
        CPA16(sbase + so,          (const char*)&g_qh[g]);
        CPA16(sbase + ATILE2 + so, (const char*)&g_ql[g]);
    }
    CPA_COMMIT();
    CPA_WAIT0();
    __syncthreads();

    uint32_t qfh[8][4], qfl[8][4];
    {
        int row = warp * 16 + ((lq & 1) ? 8 : 0) + lrow;
        #pragma unroll
        for (int ks = 0; ks < 8; ks++) {
            int col = ks * 16 + ((lq & 2) ? 8 : 0);
            uint32_t so = (uint32_t)(row * AST + col) * 2;
            LDSM4(qfh[ks], sbase + so);
            LDSM4(qfl[ks], sbase + ATILE2 + so);
        }
    }
    __syncthreads();   // all Q reads done before K overwrites tiles 0,1

    float o[16][4];
    #pragma unroll
    for (int j = 0; j < 16; j++)
        #pragma unroll
        for (int e = 0; e < 4; e++) o[j][e] = 0.f;
    float mr[2] = { -1e30f, -1e30f };
    float lr_[2] = { 0.f, 0.f };

    const int krow_b = ((lq & 2) ? 8 : 0) + lrow;
    const int kcol_b = ((lq & 1) ? 8 : 0);
    const int vrow_b = ((lq & 1) ? 8 : 0) + lrow;
    const int vcol_b = ((lq & 2) ? 8 : 0);
    const int myrow  = lane >> 2;
    const int mycol  = 2 * (lane & 3);

    // K/V group prefetch into buffer b (tiles 3b, 3b+1, 3b+2)
    auto load_kv = [&](int buf, int kb) {
        uint32_t t0 = sbase + (uint32_t)(3 * buf) * ATILE2;
        #pragma unroll
        for (int it = 0; it < 8; it++) {
            int idx = it * 256 + tid;
            int r   = idx >> 4;
            int c8  = (idx & 15) * 8;
            size_t g = base + (size_t)(kb + r) * HD + c8;
            uint32_t so = (uint32_t)(r * AST + c8) * 2;
            CPA16(t0 + so,              (const char*)&g_kh[g]);
            CPA16(t0 + ATILE2 + so,     (const char*)&g_kl[g]);
            CPA16(t0 + 2 * ATILE2 + so, (const char*)&g_vh[g]);
        }
        CPA_COMMIT();
    };

    load_kv(0, 0);

    for (int kt = 0; kt <= qt; kt++) {
        const int kb  = kt * 128;
        const int cur = kt & 1;
        if (kt < qt) {
            load_kv(cur ^ 1, kb + 128);
            CPA_WAIT1();
        } else {
            CPA_WAIT0();
        }
        __syncthreads();   // current buffer visible to all threads

        const uint32_t sKh_u = sbase + (uint32_t)(3 * cur) * ATILE2;
        const uint32_t sKl_u = sKh_u + ATILE2;
        const uint32_t sVh_u = sKh_u + 2 * ATILE2;

        // ---- S = Qh Kh^T + Qh Kl^T + Ql Kh^T ----
        float sf[16][4];
        #pragma unroll
        for (int j = 0; j < 16; j++)
            #pragma unroll
            for (int e = 0; e < 4; e++) sf[j][e] = 0.f;

        #pragma unroll
        for (int ks = 0; ks < 8; ks++) {
            #pragma unroll
            for (int jj = 0; jj < 8; jj += 2) {
                int col = ks * 16 + kcol_b;
                uint32_t so0 = (uint32_t)(((jj    ) * 16 + krow_b) * AST + col) * 2;
                uint32_t so1 = (uint32_t)(((jj + 1) * 16 + krow_b) * AST + col) * 2;
                uint32_t kfh0[4], kfl0[4], kfh1[4], kfl1[4];
                LDSM4(kfh0, sKh_u + so0);
                LDSM4(kfh1, sKh_u + so1);
                LDSM4(kfl0, sKl_u + so0);
                LDSM4(kfl1, sKl_u + so1);
                MMAH(sf[2*jj],   qfh[ks], kfh0[0], kfh0[1]);
                MMAH(sf[2*jj+1], qfh[ks], kfh0[2], kfh0[3]);
                MMAH(sf[2*jj+2], qfh[ks], kfh1[0], kfh1[1]);
                MMAH(sf[2*jj+3], qfh[ks], kfh1[2], kfh1[3]);

                MMAH(sf[2*jj],   qfh[ks], kfl0[0], kfl0[1]);
                MMAH(sf[2*jj+1], qfh[ks], kfl0[2], kfl0[3]);
                MMAH(sf[2*jj+2], qfh[ks], kfl1[0], kfl1[1]);
                MMAH(sf[2*jj+3], qfh[ks], kfl1[2], kfl1[3]);

                MMAH(sf[2*jj],   qfl[ks], kfh0[0], kfh0[1]);
                MMAH(sf[2*jj+1], qfl[ks], kfh0[2], kfh0[3]);
                MMAH(sf[2*jj+2], qfl[ks], kfh1[0], kfh1[1]);
                MMAH(sf[2*jj+3], qfl[ks], kfh1[2], kfh1[3]);
            }
        }

        // ---- online softmax ----
        const bool diag = (kt == qt);
        const int grow0 = q0 + warp * 16 + myrow;
        #pragma unroll
        for (int rr = 0; rr < 2; rr++) {
            const int grow = grow0 + rr * 8;
            float mx = -1e30f;
            #pragma unroll
            for (int j = 0; j < 16; j++) {
                #pragma unroll
                for (int e = 0; e < 2; e++) {
                    float v = sf[j][rr * 2 + e] * SCALE;
                    if (diag && (kb + j * 8 + mycol + e) > grow) v = -1e30f;
                    sf[j][rr * 2 + e] = v;
                    mx = fmaxf(mx, v);
                }
            }
            mx = fmaxf(mx, __shfl_xor_sync(0xffffffffu, mx, 1));
            mx = fmaxf(mx, __shfl_xor_sync(0xffffffffu, mx, 2));
            float mnew  = fmaxf(mr[rr], mx);
            float alpha = __expf(mr[rr] - mnew);
            mr[rr] = mnew;
            float ls = 0.f;
            #pragma unroll
            for (int j = 0; j < 16; j++) {
                #pragma unroll
                for (int e = 0; e < 2; e++) {
                    float p = __expf(sf[j][rr * 2 + e] - mnew);
                    sf[j][rr * 2 + e] = p;
                    ls += p;
                }
            }
            ls += __shfl_xor_sync(0xffffffffu, ls, 1);
            ls += __shfl_xor_sync(0xffffffffu, ls, 2);
            lr_[rr] = lr_[rr] * alpha + ls;
            #pragma unroll
            for (int j = 0; j < 16; j++) {
                o[j][rr * 2]     *= alpha;
                o[j][rr * 2 + 1] *= alpha;
            }
        }

        // ---- pack P to fp16 A-frags ----
        uint32_t pf[8][4];
        #pragma unroll
        for (int j = 0; j < 8; j++) {
            __half2 h;
            h = __floats2half2_rn(sf[2*j][0],   sf[2*j][1]);   pf[j][0] = *(uint32_t*)&h;
            h = __floats2half2_rn(sf[2*j][2],   sf[2*j][3]);   pf[j][1] = *(uint32_t*)&h;
            h = __floats2half2_rn(sf[2*j+1][0], sf[2*j+1][1]); pf[j][2] = *(uint32_t*)&h;
            h = __floats2half2_rn(sf[2*j+1][2], sf[2*j+1][3]); pf[j][3] = *(uint32_t*)&h;
        }

        // ---- O += P · Vh ----
        #pragma unroll
        for (int j = 0; j < 8; j++) {
            int row = j * 16 + vrow_b;
            #pragma unroll
            for (int dd = 0; dd < 8; dd += 2) {
                uint32_t so0 = (uint32_t)(row * AST + (dd    ) * 16 + vcol_b) * 2;
                uint32_t so1 = (uint32_t)(row * AST + (dd + 1) * 16 + vcol_b) * 2;
                uint32_t vh0[4], vh1[4];
                LDSM4T(vh0, sVh_u + so0);
                LDSM4T(vh1, sVh_u + so1);
                MMAH(o[2*dd],   pf[j], vh0[0], vh0[1]);
                MMAH(o[2*dd+1], pf[j], vh0[2], vh0[3]);
                MMAH(o[2*dd+2], pf[j], vh1[0], vh1[1]);
                MMAH(o[2*dd+3], pf[j], vh1[2], vh1[3]);
            }
        }

        __syncthreads();   // reads of buffer `cur` done (it is re-written at kt+2)
    }

    // ---- epilogue: normalize, write ctx fp16 ----
    const int b = bh >> 4;
    const int h = bh & 15;
    float inv0 = 1.0f / lr_[0];
    float inv1 = 1.0f / lr_[1];
    const int srow = q0 + warp * 16 + myrow;
    #pragma unroll
    for (int j = 0; j < 16; j++) {
        int col = j * 8 + mycol;
        #pragma unroll
        for (int rr = 0; rr < 2; rr++) {
            float v0 = o[j][rr * 2]     * (rr ? inv1 : inv0);
            float v1 = o[j][rr * 2 + 1] * (rr ? inv1 : inv0);
            size_t off = ((size_t)(b * S_) + srow + rr * 8) * H_ + h * HD + col;
            *(__half2*)&g_cf[off] = __floats2half2_rn(v0, v1);
        }
    }
}

// ---------------------------------------------------------------------------
extern "C" void kernel_launch(void* const* d_in, const int* in_sizes, int n_in,
                              void* d_out, int out_size)
{
    (void)in_sizes; (void)n_in; (void)out_size;
    const float* x  = (const float*)d_in[0];
    const float* Wq = (const float*)d_in[1];
    const float* Wk = (const float*)d_in[2];
    const float* Wv = (const float*)d_in[3];
    const float* Wo = (const float*)d_in[4];
    const float* cs = (const float*)d_in[5];
    const float* sn = (const float*)d_in[6];
    float* out = (float*)d_out;

    void *pxh, *pxl, *pwh, *pwl, *pxf, *pwvf, *pwof;
    cudaGetSymbolAddress(&pxh, g_xh);
    cudaGetSymbolAddress(&pxl, g_xl);
    cudaGetSymbolAddress(&pwh, g_wh);
    cudaGetSymbolAddress(&pwl, g_wl);
    cudaGetSymbolAddress(&pxf, g_xf);
    cudaGetSymbolAddress(&pwvf, g_wvf);
    cudaGetSymbolAddress(&pwof, g_wof);

    {
        int n4 = MTOT * H_ / 4;
        int w4 = H_ * H_ / 4;
        split_kernel<<<(n4 + 255) / 256, 256>>>(x, (__nv_bfloat16*)pxh,
                                                (__nv_bfloat16*)pxl, n4);
        split_kernel<<<(w4 + 255) / 256, 256>>>(Wq, (__nv_bfloat16*)pwh,
                                                (__nv_bfloat16*)pwl, w4);
        split_kernel<<<(w4 + 255) / 256, 256>>>(Wk, (__nv_bfloat16*)pwh + HH,
                                                (__nv_bfloat16*)pwl + HH, w4);
        cvt_kernel<<<(n4 + 255) / 256, 256>>>(x,  (__half*)pxf,  n4);
        cvt_kernel<<<(w4 + 255) / 256, 256>>>(Wv, (__half*)pwvf, w4);
        cvt_kernel<<<(w4 + 255) / 256, 256>>>(Wo, (__half*)pwof, w4);
    }

    cudaFuncSetAttribute(qkv_mma_kernel,
                         cudaFuncAttributeMaxDynamicSharedMemorySize, GEMM_SMEM);
    qkv_mma_kernel<<<dim3(H_ / 128, MTOT / 128, 3), 256, GEMM_SMEM>>>(cs, sn);

    cudaFuncSetAttribute(attn_mma_kernel,
                         cudaFuncAttributeMaxDynamicSharedMemorySize, ATTN_SMEM);
    attn_mma_kernel<<<dim3(S_ / 128, B_ * NH), 256, ATTN_SMEM>>>();

    cudaFuncSetAttribute(outproj_mma_kernel,
                         cudaFuncAttributeMaxDynamicSharedMemorySize, OUT_SMEM);
    outproj_mma_kernel<<<dim3(H_ / 128, MTOT / 128), 256, OUT_SMEM>>>(out);
}